// round 3
// baseline (speedup 1.0000x reference)
#include <cuda_runtime.h>
#include <cstdint>

#define T_STEPS 2048
#define IN_SZ   256
#define HID     512
#define BATCH   64
#define G4H     2048          // 4*HID
#define EPS_BN  1e-5f

#define NBLK    128           // recurrent grid (must be <= 148 SMs, 1 CTA/SM)
#define RTHR    128           // recurrent threads per CTA

// -------- device scratch (no runtime allocation allowed) --------
__device__ float g_bxn[(size_t)T_STEPS * G4H * BATCH];  // BN(W_ih @ x_t), 1 GiB
__device__ float g_h[2][HID * BATCH];                   // h double buffer
__device__ unsigned g_count;
__device__ volatile unsigned g_sense;

__device__ __forceinline__ float sigf(float x) { return 1.f / (1.f + expf(-x)); }

// ======================= init: reset state each launch =======================
__global__ void init_kernel() {
    int idx = blockIdx.x * blockDim.x + threadIdx.x;
    int n = HID * BATCH;
    for (int i = idx; i < n; i += gridDim.x * blockDim.x) {
        g_h[0][i] = 0.f;
        g_h[1][i] = 0.f;
    }
    if (idx == 0) { g_count = 0u; g_sense = 0u; }
}

// ======================= Kernel A: bxn = BN_ih(W_ih @ x_t) ===================
// grid: (32 row-blocks of 64, T) ; 256 threads ; tile 64 rows x 64 cols, K=256
#define WPADA 260   // padded W row stride (4*260 % 32 != 0 -> no smem bank conflict)

__global__ __launch_bounds__(256) void bnih_kernel(
    const float* __restrict__ x,           // [T, I, B]
    const float* __restrict__ wih,         // [4H, I]
    const float* __restrict__ gamma_ih,    // [4H]
    const float* __restrict__ beta_ih)     // [4H]
{
    extern __shared__ float sm[];
    float* xs = sm;                         // IN_SZ*BATCH = 16384 floats
    float* ws = sm + IN_SZ * BATCH;         // 64*WPADA floats

    int t  = blockIdx.y;
    int rb = blockIdx.x;                    // 64-row block index
    int tid = threadIdx.x;

    // stage x_t (contiguous 16384 floats)
    {
        const float4* src = (const float4*)(x + (size_t)t * IN_SZ * BATCH);
        float4* dst = (float4*)xs;
        #pragma unroll 4
        for (int i = tid; i < IN_SZ * BATCH / 4; i += 256) dst[i] = src[i];
    }
    // stage 64 W rows (padded)
    for (int i = tid; i < 64 * IN_SZ; i += 256) {
        int r = i >> 8, k = i & 255;
        ws[r * WPADA + k] = wih[(size_t)(rb * 64 + r) * IN_SZ + k];
    }
    __syncthreads();

    int rg = tid >> 4;          // 16 row-groups of 4 rows
    int cg = tid & 15;          // 16 col-groups of 4 cols

    float acc[4][4];
    #pragma unroll
    for (int i = 0; i < 4; i++)
        #pragma unroll
        for (int j = 0; j < 4; j++) acc[i][j] = 0.f;

    const float* w0 = ws + (rg * 4) * WPADA;
    const float* xp = xs + cg * 4;

    #pragma unroll 4
    for (int k = 0; k < IN_SZ; ++k) {
        float4 xv = *(const float4*)(xp + k * BATCH);
        #pragma unroll
        for (int i = 0; i < 4; i++) {
            float w = w0[i * WPADA + k];
            acc[i][0] += w * xv.x; acc[i][1] += w * xv.y;
            acc[i][2] += w * xv.z; acc[i][3] += w * xv.w;
        }
    }

    // BN per feature row over the 64 batch cols (16 cg-lanes per row)
    #pragma unroll
    for (int i = 0; i < 4; i++) {
        float s = acc[i][0] + acc[i][1] + acc[i][2] + acc[i][3];
        float q = acc[i][0]*acc[i][0] + acc[i][1]*acc[i][1]
                + acc[i][2]*acc[i][2] + acc[i][3]*acc[i][3];
        #pragma unroll
        for (int off = 8; off >= 1; off >>= 1) {
            s += __shfl_xor_sync(0xffffffffu, s, off);
            q += __shfl_xor_sync(0xffffffffu, q, off);
        }
        float mu  = s * (1.f / BATCH);
        float var = fmaxf(q * (1.f / BATCH) - mu * mu, 0.f);
        int rglob = rb * 64 + rg * 4 + i;
        float sc = rsqrtf(var + EPS_BN) * gamma_ih[rglob];
        float be = beta_ih[rglob];
        float4 o;
        o.x = (acc[i][0] - mu) * sc + be;
        o.y = (acc[i][1] - mu) * sc + be;
        o.z = (acc[i][2] - mu) * sc + be;
        o.w = (acc[i][3] - mu) * sc + be;
        *(float4*)(g_bxn + ((size_t)t * G4H + rglob) * BATCH + cg * 4) = o;
    }
}

// ======================= Kernel B: persistent recurrence =====================
// 128 CTAs x 128 threads. CTA owns hidden rows [blk*4, blk*4+4) -> 16 a-rows.
#define WPADB 516   // 2*516 % 32 != 0 -> conflict-free pairs within a warp

__global__ __launch_bounds__(RTHR) void lstm_kernel(
    const float* __restrict__ whh,        // [4H, H]
    const float* __restrict__ bias,       // [4H]
    const float* __restrict__ gamma_hh,   // [4H]
    const float* __restrict__ beta_hh,    // [4H]
    const float* __restrict__ gamma_c,    // [H]
    const float* __restrict__ beta_c,     // [H]
    float* __restrict__ out)              // [T, H, B]
{
    extern __shared__ float sm[];
    float* ws  = sm;                        // 16*WPADB
    float* hs  = ws + 16 * WPADB;           // HID*BATCH = 32768
    float* ifg = hs + HID * BATCH;          // 16*BATCH
    float* cs  = ifg + 16 * BATCH;          // 4*BATCH
    float* cst = cs + 4 * BATCH;            // 8: (mu, rstd) x 4 rows

    int tid = threadIdx.x;
    int blk = blockIdx.x;

    // load W_hh rows for our 16 a-rows (a-row local L = q*4 + j, global q*512+blk*4+j)
    for (int i = tid; i < 16 * HID; i += RTHR) {
        int L = i >> 9, k = i & 511;
        int grow = (L >> 2) * HID + blk * 4 + (L & 3);
        ws[L * WPADB + k] = whh[(size_t)grow * HID + k];
    }
    for (int i = tid; i < 4 * BATCH; i += RTHR) cs[i] = 0.f;

    // GEMM thread mapping: 8 row-groups of 2 rows x 16 col-groups of 4 cols
    int rg = tid >> 4, cg = tid & 15;
    int L0 = rg * 2, L1 = L0 + 1;
    int grow0 = (L0 >> 2) * HID + blk * 4 + (L0 & 3);
    int grow1 = (L1 >> 2) * HID + blk * 4 + (L1 & 3);
    float ghh0 = gamma_hh[grow0], bhh0 = beta_hh[grow0], bi0 = bias[grow0];
    float ghh1 = gamma_hh[grow1], bhh1 = beta_hh[grow1], bi1 = bias[grow1];

    // gate/update mapping: thread handles flat indices tid and tid+128 of 4x64
    int p0 = tid, p1 = tid + RTHR;
    int hr0 = p0 >> 6, col0 = p0 & 63;
    int hr1 = p1 >> 6, col1 = p1 & 63;
    float gc0 = gamma_c[blk * 4 + hr0], bc0 = beta_c[blk * 4 + hr0];
    float gc1 = gamma_c[blk * 4 + hr1], bc1 = beta_c[blk * 4 + hr1];

    unsigned base = g_sense;   // offset targets by live value (ncu-replay safe)
    __syncthreads();

    for (int t = 0; t < T_STEPS; ++t) {
        int cur = t & 1;
        // ---- stage h_{t-1} into smem ----
        {
            const float4* src = (const float4*)g_h[cur];
            float4* dst = (float4*)hs;
            #pragma unroll 8
            for (int i = 0; i < (HID * BATCH / 4) / RTHR; ++i)
                dst[tid + i * RTHR] = src[tid + i * RTHR];
        }
        __syncthreads();

        // ---- GEMM: a[16 x 64] = Wchunk[16 x 512] @ h[512 x 64] ----
        float a0[4] = {0.f, 0.f, 0.f, 0.f};
        float a1[4] = {0.f, 0.f, 0.f, 0.f};
        {
            const float* w0p = ws + L0 * WPADB;
            const float* w1p = ws + L1 * WPADB;
            const float* hp  = hs + cg * 4;
            #pragma unroll 4
            for (int k = 0; k < HID; ++k) {
                float4 hv = *(const float4*)(hp + k * BATCH);
                float w0 = w0p[k], w1 = w1p[k];
                a0[0] += w0 * hv.x; a0[1] += w0 * hv.y;
                a0[2] += w0 * hv.z; a0[3] += w0 * hv.w;
                a1[0] += w1 * hv.x; a1[1] += w1 * hv.y;
                a1[2] += w1 * hv.z; a1[3] += w1 * hv.w;
            }
        }

        // ---- BN(a) + bxn + bias -> ifgo in smem ----
        const float* bxt = g_bxn + (size_t)t * G4H * BATCH;
        {
            float s = a0[0] + a0[1] + a0[2] + a0[3];
            float q = a0[0]*a0[0] + a0[1]*a0[1] + a0[2]*a0[2] + a0[3]*a0[3];
            #pragma unroll
            for (int off = 8; off >= 1; off >>= 1) {
                s += __shfl_xor_sync(0xffffffffu, s, off);
                q += __shfl_xor_sync(0xffffffffu, q, off);
            }
            float mu  = s * (1.f / BATCH);
            float var = fmaxf(q * (1.f / BATCH) - mu * mu, 0.f);
            float sc  = rsqrtf(var + EPS_BN) * ghh0;
            float4 bx = *(const float4*)(bxt + (size_t)grow0 * BATCH + cg * 4);
            float4 o;
            o.x = (a0[0] - mu) * sc + bhh0 + bx.x + bi0;
            o.y = (a0[1] - mu) * sc + bhh0 + bx.y + bi0;
            o.z = (a0[2] - mu) * sc + bhh0 + bx.z + bi0;
            o.w = (a0[3] - mu) * sc + bhh0 + bx.w + bi0;
            *(float4*)(ifg + L0 * BATCH + cg * 4) = o;
        }
        {
            float s = a1[0] + a1[1] + a1[2] + a1[3];
            float q = a1[0]*a1[0] + a1[1]*a1[1] + a1[2]*a1[2] + a1[3]*a1[3];
            #pragma unroll
            for (int off = 8; off >= 1; off >>= 1) {
                s += __shfl_xor_sync(0xffffffffu, s, off);
                q += __shfl_xor_sync(0xffffffffu, q, off);
            }
            float mu  = s * (1.f / BATCH);
            float var = fmaxf(q * (1.f / BATCH) - mu * mu, 0.f);
            float sc  = rsqrtf(var + EPS_BN) * ghh1;
            float4 bx = *(const float4*)(bxt + (size_t)grow1 * BATCH + cg * 4);
            float4 o;
            o.x = (a1[0] - mu) * sc + bhh1 + bx.x + bi1;
            o.y = (a1[1] - mu) * sc + bhh1 + bx.y + bi1;
            o.z = (a1[2] - mu) * sc + bhh1 + bx.z + bi1;
            o.w = (a1[3] - mu) * sc + bhh1 + bx.w + bi1;
            *(float4*)(ifg + L1 * BATCH + cg * 4) = o;
        }
        __syncthreads();

        // ---- gates + c update (each (hr,col) owned by exactly one thread) ----
        float c0, c1, ov0, ov1;
        {
            float iv = ifg[hr0 * BATCH + col0];
            float fv = ifg[(4 + hr0) * BATCH + col0];
            float gv = ifg[(8 + hr0) * BATCH + col0];
            ov0 = ifg[(12 + hr0) * BATCH + col0];
            c0 = sigf(fv) * cs[hr0 * BATCH + col0] + sigf(iv) * tanhf(gv);
            cs[hr0 * BATCH + col0] = c0;
        }
        {
            float iv = ifg[hr1 * BATCH + col1];
            float fv = ifg[(4 + hr1) * BATCH + col1];
            float gv = ifg[(8 + hr1) * BATCH + col1];
            ov1 = ifg[(12 + hr1) * BATCH + col1];
            c1 = sigf(fv) * cs[hr1 * BATCH + col1] + sigf(iv) * tanhf(gv);
            cs[hr1 * BATCH + col1] = c1;
        }
        __syncthreads();

        // ---- BN(c): warp w reduces hidden row w ----
        {
            int w = tid >> 5, lane = tid & 31;
            float v1 = cs[w * BATCH + lane];
            float v2 = cs[w * BATCH + 32 + lane];
            float s = v1 + v2;
            float q = v1 * v1 + v2 * v2;
            #pragma unroll
            for (int off = 16; off >= 1; off >>= 1) {
                s += __shfl_xor_sync(0xffffffffu, s, off);
                q += __shfl_xor_sync(0xffffffffu, q, off);
            }
            if (lane == 0) {
                float mu  = s * (1.f / BATCH);
                float var = fmaxf(q * (1.f / BATCH) - mu * mu, 0.f);
                cst[w * 2]     = mu;
                cst[w * 2 + 1] = rsqrtf(var + EPS_BN);
            }
        }
        __syncthreads();

        // ---- h = sigmoid(o) * tanh(BN(c)) ; write out + next h buffer ----
        int nxt = cur ^ 1;
        {
            float cn = (c0 - cst[hr0 * 2]) * cst[hr0 * 2 + 1] * gc0 + bc0;
            float hv = sigf(ov0) * tanhf(cn);
            int gh = blk * 4 + hr0;
            g_h[nxt][gh * BATCH + col0] = hv;
            out[((size_t)t * HID + gh) * BATCH + col0] = hv;
        }
        {
            float cn = (c1 - cst[hr1 * 2]) * cst[hr1 * 2 + 1] * gc1 + bc1;
            float hv = sigf(ov1) * tanhf(cn);
            int gh = blk * 4 + hr1;
            g_h[nxt][gh * BATCH + col1] = hv;
            out[((size_t)t * HID + gh) * BATCH + col1] = hv;
        }
        __threadfence();

        // ---- software grid barrier (sense relative to launch-start value) ----
        __syncthreads();
        if (tid == 0) {
            unsigned target = base + (unsigned)t + 1u;
            unsigned arr = atomicAdd(&g_count, 1u);
            if (arr == (unsigned)(NBLK - 1)) {
                g_count = 0u;
                __threadfence();
                g_sense = target;
            } else {
                while (g_sense != target) { __nanosleep(64); }
            }
            __threadfence();
        }
        __syncthreads();
    }
}

// ============================== launch ======================================
extern "C" void kernel_launch(void* const* d_in, const int* in_sizes, int n_in,
                              void* d_out, int out_size) {
    const float* x        = (const float*)d_in[0];
    const float* wih      = (const float*)d_in[1];
    const float* whh      = (const float*)d_in[2];
    const float* bias     = (const float*)d_in[3];
    const float* gamma_ih = (const float*)d_in[4];
    const float* beta_ih  = (const float*)d_in[5];
    const float* gamma_hh = (const float*)d_in[6];
    const float* beta_hh  = (const float*)d_in[7];
    const float* gamma_c  = (const float*)d_in[8];
    const float* beta_c   = (const float*)d_in[9];
    float* out = (float*)d_out;

    size_t smemA = (size_t)(IN_SZ * BATCH + 64 * WPADA) * sizeof(float);
    size_t smemB = (size_t)(16 * WPADB + HID * BATCH + 16 * BATCH + 4 * BATCH + 8)
                   * sizeof(float);

    cudaFuncSetAttribute(bnih_kernel, cudaFuncAttributeMaxDynamicSharedMemorySize,
                         (int)smemA);
    cudaFuncSetAttribute(lstm_kernel, cudaFuncAttributeMaxDynamicSharedMemorySize,
                         (int)smemB);

    init_kernel<<<64, 256>>>();
    bnih_kernel<<<dim3(32, T_STEPS), 256, smemA>>>(x, wih, gamma_ih, beta_ih);
    lstm_kernel<<<NBLK, RTHR, smemB>>>(whh, bias, gamma_hh, beta_hh,
                                       gamma_c, beta_c, out);
    (void)in_sizes; (void)n_in; (void)out_size;
}

// round 4
// speedup vs baseline: 2.0115x; 2.0115x over previous
#include <cuda_runtime.h>
#include <cstdint>

#define T_STEPS 2048
#define IN_SZ   256
#define HID     512
#define BATCH   64
#define G4H     2048          // 4*HID
#define EPS_BN  1e-5f

#define NBLK    128           // recurrent grid (all co-resident, 1 CTA/SM)
#define RTHR    256           // recurrent threads per CTA (8 warps)

// -------- device scratch (no runtime allocation allowed) --------
__device__ float g_bxn[(size_t)T_STEPS * G4H * BATCH];  // BN(W_ih @ x_t)
__device__ unsigned g_count;
__device__ volatile unsigned g_sense;

__device__ __forceinline__ float sigf(float x) { return 1.f / (1.f + expf(-x)); }

// packed f32x2 FMA: c += {w,w} * x   (FFMA2 in SASS, 2x fp32 throughput)
__device__ __forceinline__ void ffma2(float2 &c, float w, float2 x) {
    float2 wv = make_float2(w, w);
    asm("fma.rn.f32x2 %0, %1, %2, %0;"
        : "+l"(reinterpret_cast<unsigned long long&>(c))
        : "l"(reinterpret_cast<unsigned long long&>(wv)),
          "l"(reinterpret_cast<unsigned long long&>(x)));
}

#define CP_ASYNC16(dst_u32, src_ptr) \
    asm volatile("cp.async.cg.shared.global [%0], [%1], 16;" \
                 :: "r"(dst_u32), "l"(src_ptr))
#define CP_COMMIT() asm volatile("cp.async.commit_group;")
#define CP_WAIT(N)  asm volatile("cp.async.wait_group " #N ";")

// ======================= init: reset barrier state ==========================
__global__ void init_kernel() {
    if (threadIdx.x == 0 && blockIdx.x == 0) { g_count = 0u; g_sense = 0u; }
}

// ======================= Kernel A: bxn = BN_ih(W_ih @ x_t) ===================
// grid: (32 row-blocks of 64, T) ; 256 threads ; tile 64 rows x 64 cols, K=256
#define WPADA 260

__global__ __launch_bounds__(256) void bnih_kernel(
    const float* __restrict__ x,           // [T, I, B]
    const float* __restrict__ wih,         // [4H, I]
    const float* __restrict__ gamma_ih,    // [4H]
    const float* __restrict__ beta_ih)     // [4H]
{
    extern __shared__ float sm[];
    float* xs = sm;                         // IN_SZ*BATCH = 16384 floats
    float* ws = sm + IN_SZ * BATCH;         // 64*WPADA floats

    int t  = blockIdx.y;
    int rb = blockIdx.x;
    int tid = threadIdx.x;

    {   // stage x_t
        const float4* src = (const float4*)(x + (size_t)t * IN_SZ * BATCH);
        float4* dst = (float4*)xs;
        #pragma unroll 4
        for (int i = tid; i < IN_SZ * BATCH / 4; i += 256) dst[i] = src[i];
    }
    for (int i = tid; i < 64 * IN_SZ; i += 256) {
        int r = i >> 8, k = i & 255;
        ws[r * WPADA + k] = wih[(size_t)(rb * 64 + r) * IN_SZ + k];
    }
    __syncthreads();

    int rg = tid >> 4;          // 16 row-groups of 4 rows
    int cg = tid & 15;          // 16 col-groups of 4 cols

    float2 acc[4][2];
    #pragma unroll
    for (int i = 0; i < 4; i++) { acc[i][0] = make_float2(0.f,0.f);
                                  acc[i][1] = make_float2(0.f,0.f); }

    const float* w0 = ws + (rg * 4) * WPADA;
    const float* xp = xs + cg * 4;

    #pragma unroll 4
    for (int k = 0; k < IN_SZ; ++k) {
        float4 xv = *(const float4*)(xp + k * BATCH);
        float2 x01 = make_float2(xv.x, xv.y);
        float2 x23 = make_float2(xv.z, xv.w);
        #pragma unroll
        for (int i = 0; i < 4; i++) {
            float w = w0[i * WPADA + k];
            ffma2(acc[i][0], w, x01);
            ffma2(acc[i][1], w, x23);
        }
    }

    #pragma unroll
    for (int i = 0; i < 4; i++) {
        float a0 = acc[i][0].x, a1 = acc[i][0].y, a2 = acc[i][1].x, a3 = acc[i][1].y;
        float s = a0 + a1 + a2 + a3;
        float q = a0*a0 + a1*a1 + a2*a2 + a3*a3;
        #pragma unroll
        for (int off = 8; off >= 1; off >>= 1) {
            s += __shfl_xor_sync(0xffffffffu, s, off);
            q += __shfl_xor_sync(0xffffffffu, q, off);
        }
        float mu  = s * (1.f / BATCH);
        float var = fmaxf(q * (1.f / BATCH) - mu * mu, 0.f);
        int rglob = rb * 64 + rg * 4 + i;
        float sc = rsqrtf(var + EPS_BN) * gamma_ih[rglob];
        float be = beta_ih[rglob];
        float4 o;
        o.x = (a0 - mu) * sc + be;
        o.y = (a1 - mu) * sc + be;
        o.z = (a2 - mu) * sc + be;
        o.w = (a3 - mu) * sc + be;
        *(float4*)(g_bxn + ((size_t)t * G4H + rglob) * BATCH + cg * 4) = o;
    }
}

// ======================= Kernel B: persistent recurrence =====================
// 128 CTAs x 256 threads. CTA owns 4 hidden rows -> 16 a-rows (4 per gate).
// Threads: kg = tid>>6 (4 K-groups of 128 k), rg = (tid>>4)&3, cg = tid&15.
// Thread tile: 4 a-rows x 4 batch over its 128-k chunk; smem reduction over kg.

// smem layout (floats):
//   ws  [16][512]      8192
//   hs  [512][64]     32768
//   red [4][16][64]    4096
//   ifg [16][64]       1024
//   cs  [4][64]         256
//   cst [8]               8   (+pad)
#define SM_WS   0
#define SM_HS   8192
#define SM_RED  40960
#define SM_IFG  45056
#define SM_CS   46080
#define SM_CST  46336
#define SM_TOT  46352

__device__ __forceinline__ void gemm32(const float* __restrict__ wsr,
                                       const float* __restrict__ hp,
                                       int kbase, float2 acc[4][2]) {
    #pragma unroll 8
    for (int kk = 0; kk < 32; ++kk) {
        int k = kbase + kk;
        float4 hv = *(const float4*)(hp + k * BATCH);
        float2 h01 = make_float2(hv.x, hv.y);
        float2 h23 = make_float2(hv.z, hv.w);
        #pragma unroll
        for (int i = 0; i < 4; ++i) {
            float w = wsr[i * HID + k];
            ffma2(acc[i][0], w, h01);
            ffma2(acc[i][1], w, h23);
        }
    }
}

__global__ __launch_bounds__(RTHR) void lstm_kernel(
    const float* __restrict__ whh,        // [4H, H]
    const float* __restrict__ bias,       // [4H]
    const float* __restrict__ gamma_hh,   // [4H]
    const float* __restrict__ beta_hh,    // [4H]
    const float* __restrict__ gamma_c,    // [H]
    const float* __restrict__ beta_c,     // [H]
    float* __restrict__ out)              // [T, H, B]
{
    extern __shared__ float sm[];
    float* ws  = sm + SM_WS;
    float* hs  = sm + SM_HS;
    float* red = sm + SM_RED;
    float* ifg = sm + SM_IFG;
    float* cs  = sm + SM_CS;
    float* cst = sm + SM_CST;

    int tid = threadIdx.x;
    int blk = blockIdx.x;

    // load W_hh rows: local a-row r -> global row (r>>2)*512 + blk*4 + (r&3)
    for (int i = tid; i < 16 * HID; i += RTHR) {
        int r = i >> 9, k = i & 511;
        int grow = (r >> 2) * HID + blk * 4 + (r & 3);
        ws[r * HID + k] = whh[(size_t)grow * HID + k];
    }
    for (int i = tid; i < 4 * BATCH; i += RTHR) cs[i] = 0.f;

    // GEMM mapping
    int kg = tid >> 6;
    int rg = (tid >> 4) & 3;
    int cg = tid & 15;
    const float* wsr = ws + (rg * 4) * HID;
    const float* hp  = hs + cg * 4;
    int kchunk = kg * 128;
    uint32_t hs_u32 = (uint32_t)__cvta_generic_to_shared(hs);
    int lt = tid & 63;

    // BN-combine mapping: warp w handles a-rows {2w, 2w+1}
    int wrp = tid >> 5, lane = tid & 31;
    int brow = 2 * wrp + (lane >> 4);          // a-row 0..15
    int bb4  = lane & 15;                       // batch col group
    int bgrow = (brow >> 2) * HID + blk * 4 + (brow & 3);
    float ghh = gamma_hh[bgrow];
    float addc = beta_hh[bgrow] + bias[bgrow];  // beta + bias
    const float* bx_ptr = g_bxn + (size_t)bgrow * BATCH + bb4 * 4;

    // gate mapping: thread owns one (hr, col)
    int hr = tid >> 6, col = tid & 63;
    float gcn = gamma_c[blk * 4 + hr], bcn = beta_c[blk * 4 + hr];

    unsigned base = g_sense;   // offset targets by live value (ncu-replay safe)
    __syncthreads();

    for (int t = 0; t < T_STEPS; ++t) {
        // ---- prefetch bxn gate inputs (consumed in epilogue) ----
        float4 bxv = *(const float4*)(bx_ptr + (size_t)t * G4H * BATCH);

        float2 acc[4][2];
        #pragma unroll
        for (int i = 0; i < 4; i++) { acc[i][0] = make_float2(0.f,0.f);
                                      acc[i][1] = make_float2(0.f,0.f); }

        if (t > 0) {
            // ---- stage own 32KB k-chunk of h = out[t-1], 4 committed sub-chunks
            const float* prev = out + (size_t)(t - 1) * HID * BATCH;
            #pragma unroll
            for (int s = 0; s < 4; ++s) {
                #pragma unroll
                for (int it = 0; it < 8; ++it) {
                    int f = lt + 64 * (8 * s + it);       // float4 idx in chunk
                    int k = kchunk + (f >> 4);
                    int b4 = f & 15;
                    int off = (k * BATCH + b4 * 4);
                    CP_ASYNC16(hs_u32 + off * 4, prev + off);
                }
                CP_COMMIT();
            }
            // ---- overlapped GEMM over sub-chunks (64-thread named barriers)
            CP_WAIT(3); asm volatile("bar.sync %0, 64;" :: "r"(1 + kg));
            gemm32(wsr, hp, kchunk +  0, acc);
            CP_WAIT(2); asm volatile("bar.sync %0, 64;" :: "r"(1 + kg));
            gemm32(wsr, hp, kchunk + 32, acc);
            CP_WAIT(1); asm volatile("bar.sync %0, 64;" :: "r"(1 + kg));
            gemm32(wsr, hp, kchunk + 64, acc);
            CP_WAIT(0); asm volatile("bar.sync %0, 64;" :: "r"(1 + kg));
            gemm32(wsr, hp, kchunk + 96, acc);
        }

        // ---- store partials for cross-kg reduction ----
        #pragma unroll
        for (int i = 0; i < 4; i++) {
            float4 v = make_float4(acc[i][0].x, acc[i][0].y,
                                   acc[i][1].x, acc[i][1].y);
            *(float4*)(red + kg * 1024 + (rg * 4 + i) * BATCH + cg * 4) = v;
        }
        __syncthreads();

        // ---- combine kg partials + BN over batch + add bxn/bias ----
        {
            float4 v0 = *(float4*)(red +        brow * BATCH + bb4 * 4);
            float4 v1 = *(float4*)(red + 1024 + brow * BATCH + bb4 * 4);
            float4 v2 = *(float4*)(red + 2048 + brow * BATCH + bb4 * 4);
            float4 v3 = *(float4*)(red + 3072 + brow * BATCH + bb4 * 4);
            float a0 = v0.x + v1.x + v2.x + v3.x;
            float a1 = v0.y + v1.y + v2.y + v3.y;
            float a2 = v0.z + v1.z + v2.z + v3.z;
            float a3 = v0.w + v1.w + v2.w + v3.w;
            float s = a0 + a1 + a2 + a3;
            float q = a0*a0 + a1*a1 + a2*a2 + a3*a3;
            #pragma unroll
            for (int off = 8; off >= 1; off >>= 1) {
                s += __shfl_xor_sync(0xffffffffu, s, off);
                q += __shfl_xor_sync(0xffffffffu, q, off);
            }
            float mu  = s * (1.f / BATCH);
            float var = fmaxf(q * (1.f / BATCH) - mu * mu, 0.f);
            float sc  = rsqrtf(var + EPS_BN) * ghh;
            float4 o;
            o.x = (a0 - mu) * sc + addc + bxv.x;
            o.y = (a1 - mu) * sc + addc + bxv.y;
            o.z = (a2 - mu) * sc + addc + bxv.z;
            o.w = (a3 - mu) * sc + addc + bxv.w;
            *(float4*)(ifg + brow * BATCH + bb4 * 4) = o;
        }
        __syncthreads();

        // ---- gates + c update (one (hr,col) per thread) ----
        float iv = ifg[hr * BATCH + col];
        float fv = ifg[(4 + hr) * BATCH + col];
        float gv = ifg[(8 + hr) * BATCH + col];
        float ov = ifg[(12 + hr) * BATCH + col];
        float c  = sigf(fv) * cs[hr * BATCH + col] + sigf(iv) * tanhf(gv);
        cs[hr * BATCH + col] = c;
        __syncthreads();

        // ---- BN(c): warps 0..3 reduce hidden row w ----
        if (wrp < 4) {
            float v1 = cs[wrp * BATCH + lane];
            float v2 = cs[wrp * BATCH + 32 + lane];
            float s = v1 + v2;
            float q = v1 * v1 + v2 * v2;
            #pragma unroll
            for (int off = 16; off >= 1; off >>= 1) {
                s += __shfl_xor_sync(0xffffffffu, s, off);
                q += __shfl_xor_sync(0xffffffffu, q, off);
            }
            if (lane == 0) {
                float mu  = s * (1.f / BATCH);
                float var = fmaxf(q * (1.f / BATCH) - mu * mu, 0.f);
                cst[wrp * 2]     = mu;
                cst[wrp * 2 + 1] = rsqrtf(var + EPS_BN);
            }
        }
        __syncthreads();

        // ---- h = sigmoid(o) * tanh(BN(c)) -> out[t] (also next step's h) ----
        {
            float cn = (c - cst[hr * 2]) * cst[hr * 2 + 1] * gcn + bcn;
            float hv = sigf(ov) * tanhf(cn);
            out[((size_t)t * HID + blk * 4 + hr) * BATCH + col] = hv;
        }
        __threadfence();

        // ---- software grid barrier ----
        __syncthreads();
        if (tid == 0) {
            unsigned target = base + (unsigned)t + 1u;
            unsigned arr = atomicAdd(&g_count, 1u);
            if (arr == (unsigned)(NBLK - 1)) {
                g_count = 0u;
                __threadfence();
                g_sense = target;
            } else {
                while (g_sense != target) { __nanosleep(64); }
            }
            __threadfence();
        }
        __syncthreads();
    }
}

// ============================== launch ======================================
extern "C" void kernel_launch(void* const* d_in, const int* in_sizes, int n_in,
                              void* d_out, int out_size) {
    const float* x        = (const float*)d_in[0];
    const float* wih      = (const float*)d_in[1];
    const float* whh      = (const float*)d_in[2];
    const float* bias     = (const float*)d_in[3];
    const float* gamma_ih = (const float*)d_in[4];
    const float* beta_ih  = (const float*)d_in[5];
    const float* gamma_hh = (const float*)d_in[6];
    const float* beta_hh  = (const float*)d_in[7];
    const float* gamma_c  = (const float*)d_in[8];
    const float* beta_c   = (const float*)d_in[9];
    float* out = (float*)d_out;

    size_t smemA = (size_t)(IN_SZ * BATCH + 64 * WPADA) * sizeof(float);
    size_t smemB = (size_t)SM_TOT * sizeof(float);

    cudaFuncSetAttribute(bnih_kernel, cudaFuncAttributeMaxDynamicSharedMemorySize,
                         (int)smemA);
    cudaFuncSetAttribute(lstm_kernel, cudaFuncAttributeMaxDynamicSharedMemorySize,
                         (int)smemB);

    init_kernel<<<1, 32>>>();
    bnih_kernel<<<dim3(32, T_STEPS), 256, smemA>>>(x, wih, gamma_ih, beta_ih);
    lstm_kernel<<<NBLK, RTHR, smemB>>>(whh, bias, gamma_hh, beta_hh,
                                       gamma_c, beta_c, out);
    (void)in_sizes; (void)n_in; (void)out_size;
}